// round 16
// baseline (speedup 1.0000x reference)
#include <cuda_runtime.h>
#include <cuda_fp16.h>
#include <float.h>
#include <stdint.h>

// ---------------- problem constants ----------------
#define BB   2
#define V_   12000
#define VP   12001
#define LSP  16
#define M_TOT (BB*VP)          // 24002
#define NCHUNK 94

typedef __half hf;

// ---------------- scratch (device globals) ----------------
__device__ hf g_Xh [M_TOT*512];
__device__ hf g_Hbh[M_TOT*384], g_Hbl[M_TOT*384];   // [pfs(256) | fs3(128)]
__device__ hf g_T1h[M_TOT*256];
__device__ hf g_T2h[M_TOT*256];
__device__ hf g_F1h[M_TOT*128], g_F1l[M_TOT*128];
__device__ hf g_F2h[M_TOT*128];
__device__ hf g_H2h[M_TOT*128], g_H2l[M_TOT*128];
__device__ hf g_Wpth[512*256],   g_Wptl[512*256];
__device__ hf g_R1ah[4096*256],  g_R1al[4096*256];
__device__ hf g_R1bh[4096*256],  g_R1bl[4096*256];
__device__ hf g_Wmh [256*128],   g_Wml [256*128];
__device__ hf g_RSh [6*2048*128],g_RSl [6*2048*128];
__device__ hf g_Wo1h[384*256],   g_Wo1l[384*256];
__device__ hf g_Wo2h[256*128],   g_Wo2l[256*128];
__device__ float g_P  [2][M_TOT*256];   // split-K fp32 partials
__device__ float g_part [BB*NCHUNK*128];
__device__ float g_gfs  [BB*128];
__device__ float g_gterm[BB*256];

enum { F_RELU = 1, F_ZDUM = 2, F_WLO = 4 };

// ---------------- helpers ----------------
__device__ __forceinline__ uint32_t s2u(const void* p) {
    uint32_t a;
    asm("{ .reg .u64 t; cvta.to.shared.u64 t, %1; cvt.u32.u64 %0, t; }" : "=r"(a) : "l"(p));
    return a;
}
__device__ __forceinline__ void ldsm4(uint32_t addr, uint32_t* r) {
    asm volatile("ldmatrix.sync.aligned.m8n8.x4.shared.b16 {%0,%1,%2,%3}, [%4];"
        : "=r"(r[0]), "=r"(r[1]), "=r"(r[2]), "=r"(r[3]) : "r"(addr));
}
__device__ __forceinline__ void ldsm4t(uint32_t addr, uint32_t* r) {
    asm volatile("ldmatrix.sync.aligned.m8n8.x4.trans.shared.b16 {%0,%1,%2,%3}, [%4];"
        : "=r"(r[0]), "=r"(r[1]), "=r"(r[2]), "=r"(r[3]) : "r"(addr));
}
__device__ __forceinline__ void mma_f16(float* c, const uint32_t* a, const uint32_t* b) {
    asm volatile("mma.sync.aligned.m16n8k16.row.col.f32.f16.f16.f32 "
        "{%0,%1,%2,%3}, {%4,%5,%6,%7}, {%8,%9}, {%0,%1,%2,%3};"
        : "+f"(c[0]), "+f"(c[1]), "+f"(c[2]), "+f"(c[3])
        : "r"(a[0]), "r"(a[1]), "r"(a[2]), "r"(a[3]), "r"(b[0]), "r"(b[1]));
}
// L2-only cp.async (no L1 allocation)
__device__ __forceinline__ void cpa(uint32_t dst, const void* src) {
    asm volatile("cp.async.cg.shared.global [%0], [%1], 16;" :: "r"(dst), "l"(src) : "memory");
}
#define CPCOMMIT() asm volatile("cp.async.commit_group;" ::: "memory")
#define CPWAIT1()  asm volatile("cp.async.wait_group 1;" ::: "memory")

__device__ __forceinline__ void fsplit2(float f, hf& h, hf& l) {
    h = __float2half_rn(f);
    l = __float2half_rn(f - __half2float(h));
}
__device__ __forceinline__ float pjoin(const hf* H, const hf* L, long i) {
    return __half2float(H[i]) + __half2float(L[i]);
}

// ---------------- smem geometry ----------------
#define APITCH 80
#define ASTG   (128*APITCH)              // 10240 (single A plane)

// ---------------- mma.sync fp16x2 fused (gather-)GEMM, 3-stage cp.async ----------------
// NB: block N tile; MW: m16-frags per warp; OCC: min CTAs/SM. 8 warps.
// Split-K: grid.z = #splits, K = per-split K, kbase = z*K; raw fp32 partial to Po.
template<int NB, int MW, int OCC>
__global__ __launch_bounds__(256, OCC)
void gemm_tc(const hf* __restrict__ Ah,
             const hf* __restrict__ Wh, const hf* __restrict__ Wl,
             hf* __restrict__ Oh, hf* __restrict__ Ol,
             float* __restrict__ Po, long pstride,
             const int* __restrict__ idx,
             const float* __restrict__ bias, const float* __restrict__ bias_b,
             const hf* __restrict__ Rh, const hf* __restrict__ Rl,
             int M, int N, int K, int lda, int ldn, int ldo, int ldr,
             int logC, int flags)
{
    constexpr int BP      = NB * 2 + 16;
    constexpr int BPL     = 32 * BP;
    constexpr int STG     = ASTG + 2 * BPL;
    constexpr int BCH     = 8 * NB;
    constexpr int WARPS_M = 128 / (MW * 16);
    static_assert(WARPS_M * (NB / 32) == 8, "8 warps");

    extern __shared__ char smem[];
    const uint32_t sbs = s2u(smem);
    const int t = threadIdx.x, wid = t >> 5, lane = t & 31;
    const int bm0 = blockIdx.x * 128, bn0 = blockIdx.y * NB;
    const int wm = (wid % WARPS_M) * (MW * 16), wn = (wid / WARPS_M) * 32;
    const int kbase = blockIdx.z * K;

    const int r0 = t >> 2, c4 = t & 3;
    const int cmask = (1 << logC) - 1;
    long ab[2]; const int* ib[2];
#pragma unroll
    for (int r = 0; r < 2; r++) {
        int m = bm0 + r0 + r * 64; if (m >= M) m = M - 1;
        int bI = m / VP, v = m - bI * VP;
        if (idx) { ab[r] = (long)bI * VP * lda; ib[r] = idx + v * LSP; }
        else     { ab[r] = (long)m * lda;       ib[r] = nullptr; }
    }

    const uint32_t la15 = lane & 15, lhi = lane >> 4, l7 = lane & 7, l8 = (lane >> 3) & 1;
    const int nkt = K >> 5;

    float acc[MW][4][4];
#pragma unroll
    for (int i = 0; i < MW; i++)
#pragma unroll
        for (int j = 0; j < 4; j++)
#pragma unroll
            for (int r = 0; r < 4; r++) acc[i][j][r] = 0.f;

    auto issue = [&](int kt, int p) {
        const int k0 = kbase + (kt << 5);
        const uint32_t base = sbs + p * STG;
#pragma unroll
        for (int r = 0; r < 2; r++) {
            long off = idx ? (ab[r] + (long)ib[r][k0 >> logC] * lda + (k0 & cmask))
                           : (ab[r] + k0);
            cpa(base + (r0 + r * 64) * APITCH + c4 * 16, Ah + off + c4 * 8);
        }
#pragma unroll
        for (int i = t; i < BCH; i += 256) {
            const int pl  = i / (4 * NB);
            const int rem = i - pl * (4 * NB);
            const int row = rem / (NB / 8);
            const int col = rem - row * (NB / 8);
            const hf* Wp = pl ? Wl : Wh;
            cpa(base + ASTG + pl * BPL + row * BP + col * 16,
                Wp + (long)(k0 + row) * ldn + bn0 + col * 8);
        }
        CPCOMMIT();
    };

    issue(0, 0);
    if (nkt > 1) issue(1, 1); else CPCOMMIT();

    for (int kt = 0; kt < nkt; kt++) {
        const int p = kt % 3;
        CPWAIT1();
        __syncthreads();
        const uint32_t base = sbs + p * STG;
#pragma unroll
        for (int ks = 0; ks < 2; ks++) {
            uint32_t a[MW][4];
#pragma unroll
            for (int i = 0; i < MW; i++)
                ldsm4(base + (wm + i * 16 + la15) * APITCH + (ks * 16 + lhi * 8) * 2, a[i]);
            const uint32_t bo = base + ASTG + (uint32_t)(ks * 16 + l7 + l8 * 8) * BP
                               + (wn + lhi * 8) * 2;
            uint32_t bh[8], bl[8];
            ldsm4t(bo,            bh);
            ldsm4t(bo + 32,       bh + 4);
            ldsm4t(bo + BPL,      bl);
            ldsm4t(bo + BPL + 32, bl + 4);
#pragma unroll
            for (int i = 0; i < MW; i++)
#pragma unroll
                for (int nf = 0; nf < 4; nf++) mma_f16(acc[i][nf], a[i], bh + nf * 2);
#pragma unroll
            for (int i = 0; i < MW; i++)
#pragma unroll
                for (int nf = 0; nf < 4; nf++) mma_f16(acc[i][nf], a[i], bl + nf * 2);
        }
        if (kt + 2 < nkt) issue(kt + 2, (kt + 2) % 3);
        else CPCOMMIT();
    }

    // ---- epilogue
    if (Po) {   // raw fp32 partial (split-K)
        float* P = Po + (long)blockIdx.z * pstride;
#pragma unroll
        for (int i = 0; i < MW; i++) {
#pragma unroll
            for (int hh = 0; hh < 2; hh++) {
                const int m = bm0 + wm + i * 16 + (lane >> 2) + hh * 8;
                if (m >= M) continue;
                const long orow = (long)m * ldo;
#pragma unroll
                for (int nf = 0; nf < 4; nf++) {
                    const int n = bn0 + wn + nf * 8 + 2 * (lane & 3);
                    float2 v2;
                    v2.x = acc[i][nf][hh * 2 + 0];
                    v2.y = acc[i][nf][hh * 2 + 1];
                    *(float2*)(P + orow + n) = v2;
                }
            }
        }
        return;
    }
    const bool wlo = (flags & F_WLO) != 0;
#pragma unroll
    for (int i = 0; i < MW; i++) {
#pragma unroll
        for (int hh = 0; hh < 2; hh++) {
            const int m = bm0 + wm + i * 16 + (lane >> 2) + hh * 8;
            if (m >= M) continue;
            const int bI = m / VP, v = m - bI * VP;
            const bool zd = (flags & F_ZDUM) && (v == V_);
            const long orow = (long)m * ldo;
            const long rrow = (long)m * ldr;
#pragma unroll
            for (int nf = 0; nf < 4; nf++) {
                const int n = bn0 + wn + nf * 8 + 2 * (lane & 3);
                float f0 = acc[i][nf][hh * 2 + 0];
                float f1 = acc[i][nf][hh * 2 + 1];
                if (bias)   { f0 += bias[n];            f1 += bias[n + 1]; }
                if (bias_b) { f0 += bias_b[bI * N + n]; f1 += bias_b[bI * N + n + 1]; }
                if (Rh)     { f0 += pjoin(Rh, Rl, rrow + n); f1 += pjoin(Rh, Rl, rrow + n + 1); }
                if (flags & F_RELU) { f0 = fmaxf(f0, 0.f); f1 = fmaxf(f1, 0.f); }
                if (zd) { f0 = 0.f; f1 = 0.f; }
                hf h0 = __float2half_rn(f0);
                hf h1 = __float2half_rn(f1);
                __half2 ph; ph.x = h0; ph.y = h1;
                *(__half2*)(Oh + orow + n) = ph;
                if (wlo) {
                    __half2 pl2;
                    pl2.x = __float2half_rn(f0 - __half2float(h0));
                    pl2.y = __float2half_rn(f1 - __half2float(h1));
                    *(__half2*)(Ol + orow + n) = pl2;
                }
            }
        }
    }
}

// ---------------- split-K combiner (vectorized x4), generalized ----------------
// out[m, ldo + n] = relu(p0+p1 (+bias) (+bias_b[b]) (+res)) ; zero dummy row; optional lo plane.
__global__ void comb_k(const float* __restrict__ P0, const float* __restrict__ P1,
                       const float* __restrict__ bias, const float* __restrict__ bias_b,
                       const hf* __restrict__ Rh, const hf* __restrict__ Rl, int ldr,
                       hf* __restrict__ Oh, hf* __restrict__ Ol, int ldo)
{
    long q = (long)blockIdx.x * 256 + threadIdx.x;      // quad index
    if (q >= (long)M_TOT * 64) return;
    long i = q * 4;
    int m = (int)(i >> 8), n = (int)(i & 255);
    int bI = m / VP, v = m - bI * VP;
    float4 a = *(const float4*)(P0 + i);
    float4 b = *(const float4*)(P1 + i);
    float f[4] = { a.x + b.x, a.y + b.y, a.z + b.z, a.w + b.w };
    if (bias) {
        float4 c = *(const float4*)(bias + n);
        f[0] += c.x; f[1] += c.y; f[2] += c.z; f[3] += c.w;
    }
    if (bias_b) {
        float4 c = *(const float4*)(bias_b + bI * 256 + n);
        f[0] += c.x; f[1] += c.y; f[2] += c.z; f[3] += c.w;
    }
    if (Rh) {
        long r = (long)m * ldr + n;
        const __half2* rh = (const __half2*)(Rh + r);
        const __half2* rl = (const __half2*)(Rl + r);
        float2 h0 = __half22float2(rh[0]), h1 = __half22float2(rh[1]);
        float2 l0 = __half22float2(rl[0]), l1 = __half22float2(rl[1]);
        f[0] += h0.x + l0.x; f[1] += h0.y + l0.y;
        f[2] += h1.x + l1.x; f[3] += h1.y + l1.y;
    }
#pragma unroll
    for (int j = 0; j < 4; j++) {
        f[j] = fmaxf(f[j], 0.f);
        if (v == V_) f[j] = 0.f;
    }
    long o = (long)m * ldo + n;
    __half2 o0; o0.x = __float2half_rn(f[0]); o0.y = __float2half_rn(f[1]);
    __half2 o1; o1.x = __float2half_rn(f[2]); o1.y = __float2half_rn(f[3]);
    *(__half2*)(Oh + o)     = o0;
    *(__half2*)(Oh + o + 2) = o1;
    if (Ol) {
        __half2 q0, q1;
        q0.x = __float2half_rn(f[0] - __half2float(o0.x));
        q0.y = __float2half_rn(f[1] - __half2float(o0.y));
        q1.x = __float2half_rn(f[2] - __half2float(o1.x));
        q1.y = __float2half_rn(f[3] - __half2float(o1.y));
        *(__half2*)(Ol + o)     = q0;
        *(__half2*)(Ol + o + 2) = q1;
    }
}

// ---------------- prep kernels ----------------
__global__ void xprep(const float* __restrict__ x, hf* __restrict__ Xh)
{
    long i = (long)blockIdx.x * 256 + threadIdx.x;
    if (i >= (long)M_TOT * 512) return;
    int m = (int)(i >> 9), k = (int)(i & 511);
    int b = m / VP, v = m - b * VP;
    float val = 0.f;
    if (v < V_ && k < 479) val = x[((long)(b * V_ + v)) * 479 + k];
    Xh[i] = __float2half_rn(val);
}

#define NSEG 12
struct WSegs {
    const float* src[NSEG];
    hf* oh[NSEG]; hf* ol[NSEG];
    int N[NSEG]; int K[NSEG];
    long n[NSEG];
};
__global__ void wprep_all(WSegs s)
{
    const int seg = blockIdx.y;
    long i = (long)blockIdx.x * 256 + threadIdx.x;
    if (i >= s.n[seg]) return;
    const int N = s.N[seg];
    const int k = (int)(i / N);
    float v = (k < s.K[seg]) ? s.src[seg][i] : 0.f;
    fsplit2(v, s.oh[seg][i], s.ol[seg][i]);
}

// ---------------- maxpool / gterm / final ----------------
__global__ void maxpool1(const hf* __restrict__ fh, const hf* __restrict__ fl)
{
    int chunk = blockIdx.x, b = blockIdx.y, n = threadIdx.x;
    int v0 = chunk * 128;
    float m = -FLT_MAX;
    for (int i = 0; i < 128; i++) {
        int v = v0 + i;
        if (v < V_) m = fmaxf(m, pjoin(fh, fl, (long)(b * VP + v) * 128 + n));
    }
    g_part[(b * NCHUNK + chunk) * 128 + n] = m;
}
__global__ void maxpool2()
{
    int b = blockIdx.x, n = threadIdx.x;
    float m = -FLT_MAX;
    for (int c = 0; c < NCHUNK; c++) m = fmaxf(m, g_part[(b * NCHUNK + c) * 128 + n]);
    g_gfs[b * 128 + n] = m;
}
__global__ void gterm_k(const float* __restrict__ Wo1)
{
    int b = blockIdx.x, n = threadIdx.x;
    float s = 0.f;
    for (int c = 0; c < 128; c++)
        s = fmaf(g_gfs[b * 128 + c], Wo1[(384 + c) * 256 + n], s);
    g_gterm[b * 256 + n] = s;
}
__global__ void out_k(const hf* __restrict__ h2h, const hf* __restrict__ h2l,
                      const float* __restrict__ Wo3, const float* __restrict__ bo3,
                      float* __restrict__ out)
{
    __shared__ float w[384];
    int t = threadIdx.x;
    if (t < 128) { w[t] = Wo3[t]; w[t + 128] = Wo3[t + 128]; w[t + 256] = Wo3[t + 256]; }
    __syncthreads();
    int warp = t >> 5, lane = t & 31;
    int u = blockIdx.x * 4 + warp;
    if (u >= BB * V_) return;
    int b = u / V_, v = u - b * V_;
    long row = (long)(b * VP + v) * 128;
    float s0 = 0.f, s1 = 0.f, s2 = 0.f;
    for (int c = lane; c < 128; c += 32) {
        float h = pjoin(h2h, h2l, row + c);
        s0 = fmaf(h, w[c * 3 + 0], s0);
        s1 = fmaf(h, w[c * 3 + 1], s1);
        s2 = fmaf(h, w[c * 3 + 2], s2);
    }
    for (int o = 16; o > 0; o >>= 1) {
        s0 += __shfl_down_sync(0xffffffffu, s0, o);
        s1 += __shfl_down_sync(0xffffffffu, s1, o);
        s2 += __shfl_down_sync(0xffffffffu, s2, o);
    }
    if (lane == 0) {
        out[u * 3 + 0] = s0 + bo3[0];
        out[u * 3 + 1] = s1 + bo3[1];
        out[u * 3 + 2] = s2 + bo3[2];
    }
}

// ---------------- host orchestration ----------------
static void* sym(const void* s) { void* p; cudaGetSymbolAddress(&p, s); return p; }

#define SMEM128 (3*(ASTG + 2*32*(128*2+16)))   // 82944
#define SMEM64  (3*(ASTG + 2*32*(64*2+16)))    // 58368
#define PSTRIDE ((long)M_TOT*256)

static void G128(const hf* Ah, const hf* Wh, const hf* Wl,
                 hf* Oh, hf* Ol, const int* idx, const float* bias, const float* bb,
                 const hf* Rh, const hf* Rl,
                 int N, int K, int lda, int ldn, int ldo, int ldr, int logC, int flags)
{
    dim3 grid((M_TOT + 127) / 128, N / 128, 1);
    gemm_tc<128, 4, 2><<<grid, 256, SMEM128>>>(Ah, Wh, Wl, Oh, Ol, nullptr, 0,
        idx, bias, bb, Rh, Rl, M_TOT, N, K, lda, ldn, ldo, ldr, logC, flags);
}
// split-K x2, raw fp32 partials
static void G128S(const hf* Ah, const hf* Wh, const hf* Wl, float* Po,
                  const int* idx, int N, int Khalf, int lda, int ldn, int logC)
{
    dim3 grid((M_TOT + 127) / 128, N / 128, 2);
    gemm_tc<128, 4, 2><<<grid, 256, SMEM128>>>(Ah, Wh, Wl, nullptr, nullptr, Po, PSTRIDE,
        idx, nullptr, nullptr, nullptr, nullptr, M_TOT, N, Khalf, lda, ldn, N, 0, logC, 0);
}
static void G64(const hf* Ah, const hf* Wh, const hf* Wl,
                hf* Oh, hf* Ol, const int* idx, const float* bias, const float* bb,
                const hf* Rh, const hf* Rl,
                int N, int K, int lda, int ldn, int ldo, int ldr, int logC, int flags)
{
    dim3 grid((M_TOT + 127) / 128, N / 64, 1);
    gemm_tc<64, 2, 3><<<grid, 256, SMEM64>>>(Ah, Wh, Wl, Oh, Ol, nullptr, 0,
        idx, bias, bb, Rh, Rl, M_TOT, N, K, lda, ldn, ldo, ldr, logC, flags);
}

extern "C" void kernel_launch(void* const* d_in, const int* in_sizes, int n_in,
                              void* d_out, int out_size)
{
    (void)in_sizes; (void)n_in; (void)out_size;
    const float* x       = (const float*)d_in[0];
    const int*   sidx    = (const int*)  d_in[1];
    const float* W_point = (const float*)d_in[2];
    const float* res1_W  = (const float*)d_in[3];
    const float* res1_b  = (const float*)d_in[4];
    const float* W_mid   = (const float*)d_in[5];
    const float* ress_W  = (const float*)d_in[6];
    const float* ress_b  = (const float*)d_in[7];
    const float* Wo1     = (const float*)d_in[8];
    const float* bo1     = (const float*)d_in[9];
    const float* Wo2     = (const float*)d_in[10];
    const float* bo2     = (const float*)d_in[11];
    const float* Wo3     = (const float*)d_in[12];
    const float* bo3     = (const float*)d_in[13];
    float* out = (float*)d_out;

    cudaFuncSetAttribute((const void*)gemm_tc<128, 4, 2>,
                         cudaFuncAttributeMaxDynamicSharedMemorySize, SMEM128);
    cudaFuncSetAttribute((const void*)gemm_tc<64, 2, 3>,
                         cudaFuncAttributeMaxDynamicSharedMemorySize, SMEM64);

    hf *Xh = (hf*)sym(g_Xh);
    hf *Hbh = (hf*)sym(g_Hbh), *Hbl = (hf*)sym(g_Hbl);
    hf *T1h = (hf*)sym(g_T1h);
    hf *T2h = (hf*)sym(g_T2h);
    hf *F1h = (hf*)sym(g_F1h), *F1l = (hf*)sym(g_F1l);
    hf *F2h = (hf*)sym(g_F2h);
    hf *H2h = (hf*)sym(g_H2h), *H2l = (hf*)sym(g_H2l);
    hf *Wpth = (hf*)sym(g_Wpth), *Wptl = (hf*)sym(g_Wptl);
    hf *R1ah = (hf*)sym(g_R1ah), *R1al = (hf*)sym(g_R1al);
    hf *R1bh = (hf*)sym(g_R1bh), *R1bl = (hf*)sym(g_R1bl);
    hf *Wmh  = (hf*)sym(g_Wmh),  *Wml  = (hf*)sym(g_Wml);
    hf *RSh  = (hf*)sym(g_RSh),  *RSl  = (hf*)sym(g_RSl);
    hf *Wo1h = (hf*)sym(g_Wo1h), *Wo1l = (hf*)sym(g_Wo1l);
    hf *Wo2h = (hf*)sym(g_Wo2h), *Wo2l = (hf*)sym(g_Wo2l);
    float* gterm = (float*)sym(g_gterm);
    float* P = (float*)sym(g_P);
    float* P0 = P;
    float* P1 = P + PSTRIDE;

    // ---- prep
    xprep<<<(unsigned)(((long)M_TOT * 512 + 255) / 256), 256>>>(x, Xh);
    {
        WSegs s;
        int si = 0;
        auto add = [&](const float* src, hf* oh, hf* ol, int K, int N, int Kpad) {
            s.src[si] = src; s.oh[si] = oh; s.ol[si] = ol;
            s.N[si] = N; s.K[si] = K; s.n[si] = (long)Kpad * N; si++;
        };
        add(W_point, Wpth, Wptl, 479, 256, 512);
        add(res1_W,              R1ah, R1al, 4096, 256, 4096);
        add(res1_W + 4096 * 256, R1bh, R1bl, 4096, 256, 4096);
        add(W_mid, Wmh, Wml, 256, 128, 256);
        for (int j = 0; j < 6; j++)
            add(ress_W + (long)j * 2048 * 128, RSh + (long)j * 2048 * 128,
                RSl + (long)j * 2048 * 128, 2048, 128, 2048);
        add(Wo1, Wo1h, Wo1l, 384, 256, 384);
        add(Wo2, Wo2h, Wo2l, 256, 128, 256);
        wprep_all<<<dim3(4096, NSEG), 256>>>(s);
    }

    const unsigned CBLK = (unsigned)(((long)M_TOT * 64 + 255) / 256);

    // 1) pfs = relu(x @ W_point) -> Hb cols 0:256   (split-K x2: 512 = 2x256)
    G128S(Xh, Wpth, Wptl, P, nullptr, 256, 256, 512, 256, 0);
    comb_k<<<CBLK, 256>>>(P0, P1, nullptr, nullptr, nullptr, nullptr, 0, Hbh, Hbl, 384);
    // 2) res1 conv1 (K=4096) — split-K x2 + combine
    G128S(Hbh, R1ah, R1al, P, sidx, 256, 2048, 384, 256, 8);
    comb_k<<<CBLK, 256>>>(P0, P1, res1_b, nullptr, nullptr, nullptr, 0, T1h, nullptr, 256);
    // 3) res1 conv2 + residual(pfs) — split-K x2 + combine
    G128S(T1h, R1bh, R1bl, P, sidx, 256, 2048, 256, 256, 8);
    comb_k<<<CBLK, 256>>>(P0, P1, res1_b + 256, nullptr, Hbh, Hbl, 384, T2h, nullptr, 256);
    // 4) fs = (r1 @ W_mid) * zp
    G64(T2h, Wmh, Wml, F1h, F1l, nullptr, nullptr, nullptr, nullptr, nullptr,
        128, 256, 256, 128, 128, 0, 0, F_ZDUM | F_WLO);
    // 5) masked global max-pool
    maxpool1<<<dim3(NCHUNK, BB), 128>>>(F1h, F1l);
    maxpool2<<<BB, 128>>>();
    // 6) three residual blocks (C=128); block 3 conv2 writes Hb cols 256:384
    for (int i = 0; i < 3; i++) {
        const hf* W0h = RSh + (long)(i * 2 + 0) * 2048 * 128;
        const hf* W0l = RSl + (long)(i * 2 + 0) * 2048 * 128;
        const hf* W1h = RSh + (long)(i * 2 + 1) * 2048 * 128;
        const hf* W1l = RSl + (long)(i * 2 + 1) * 2048 * 128;
        const float* b0 = ress_b + (i * 2 + 0) * 128;
        const float* b1 = ress_b + (i * 2 + 1) * 128;
        G64(F1h, W0h, W0l, F2h, nullptr, sidx, b0, nullptr, nullptr, nullptr,
            128, 2048, 128, 128, 128, 0, 7, F_RELU | F_ZDUM);
        if (i < 2)
            G64(F2h, W1h, W1l, F1h, F1l, sidx, b1, nullptr, F1h, F1l,
                128, 2048, 128, 128, 128, 128, 7, F_RELU | F_ZDUM | F_WLO);
        else
            G64(F2h, W1h, W1l, Hbh + 256, nullptr, sidx, b1, nullptr, F1h, F1l,
                128, 2048, 128, 128, 384, 128, 7, F_RELU | F_ZDUM);
    }
    // 7) gterm[b] = gfs[b] @ Wo1[384:512]
    gterm_k<<<BB, 256>>>(Wo1);
    // 8) h1 = relu([pfs|fs] @ Wo1[0:384] + bo1 + gterm)  (split-K x2: 384 = 2x192)
    G128S(Hbh, Wo1h, Wo1l, P, nullptr, 256, 192, 384, 256, 0);
    comb_k<<<CBLK, 256>>>(P0, P1, bo1, gterm, nullptr, nullptr, 0, T1h, nullptr, 256);
    // 9) h2 = relu(h1 @ Wo2 + bo2)
    G64(T1h, Wo2h, Wo2l, H2h, H2l, nullptr, bo2, nullptr, nullptr, nullptr,
        128, 256, 256, 128, 128, 0, 0, F_RELU | F_WLO);
    // 10) out = h2 @ Wo3 + bo3
    out_k<<<(BB * V_ + 3) / 4, 128>>>(H2h, H2l, Wo3, bo3, out);
}

// round 17
// speedup vs baseline: 1.0182x; 1.0182x over previous
#include <cuda_runtime.h>
#include <cuda_fp16.h>
#include <float.h>
#include <stdint.h>

// ---------------- problem constants ----------------
#define BB   2
#define V_   12000
#define VP   12001
#define LSP  16
#define M_TOT (BB*VP)          // 24002
#define NCHUNK 94

typedef __half hf;

// ---------------- scratch (device globals) ----------------
__device__ hf g_Xh [M_TOT*512];
__device__ hf g_Hbh[M_TOT*384], g_Hbl[M_TOT*384];   // [pfs(256) | fs3(128)]
__device__ hf g_T1h[M_TOT*256];
__device__ hf g_T2h[M_TOT*256];
__device__ hf g_F1h[M_TOT*128], g_F1l[M_TOT*128];
__device__ hf g_F2h[M_TOT*128];
__device__ hf g_H2h[M_TOT*128], g_H2l[M_TOT*128];
__device__ hf g_Wpth[512*256],   g_Wptl[512*256];
__device__ hf g_R1ah[4096*256],  g_R1al[4096*256];
__device__ hf g_R1bh[4096*256],  g_R1bl[4096*256];
__device__ hf g_Wmh [256*128],   g_Wml [256*128];
__device__ hf g_RSh [6*2048*128],g_RSl [6*2048*128];
__device__ hf g_Wo1h[384*256],   g_Wo1l[384*256];
__device__ hf g_Wo2h[256*128],   g_Wo2l[256*128];
__device__ float g_P  [2][M_TOT*256];   // split-K fp32 partials
__device__ float g_part [BB*NCHUNK*128];
__device__ float g_gfs  [BB*128];
__device__ float g_gterm[BB*256];

enum { F_RELU = 1, F_ZDUM = 2, F_WLO = 4 };

// ---------------- helpers ----------------
__device__ __forceinline__ uint32_t s2u(const void* p) {
    uint32_t a;
    asm("{ .reg .u64 t; cvta.to.shared.u64 t, %1; cvt.u32.u64 %0, t; }" : "=r"(a) : "l"(p));
    return a;
}
__device__ __forceinline__ void ldsm4(uint32_t addr, uint32_t* r) {
    asm volatile("ldmatrix.sync.aligned.m8n8.x4.shared.b16 {%0,%1,%2,%3}, [%4];"
        : "=r"(r[0]), "=r"(r[1]), "=r"(r[2]), "=r"(r[3]) : "r"(addr));
}
__device__ __forceinline__ void ldsm4t(uint32_t addr, uint32_t* r) {
    asm volatile("ldmatrix.sync.aligned.m8n8.x4.trans.shared.b16 {%0,%1,%2,%3}, [%4];"
        : "=r"(r[0]), "=r"(r[1]), "=r"(r[2]), "=r"(r[3]) : "r"(addr));
}
__device__ __forceinline__ void mma_f16(float* c, const uint32_t* a, const uint32_t* b) {
    asm volatile("mma.sync.aligned.m16n8k16.row.col.f32.f16.f16.f32 "
        "{%0,%1,%2,%3}, {%4,%5,%6,%7}, {%8,%9}, {%0,%1,%2,%3};"
        : "+f"(c[0]), "+f"(c[1]), "+f"(c[2]), "+f"(c[3])
        : "r"(a[0]), "r"(a[1]), "r"(a[2]), "r"(a[3]), "r"(b[0]), "r"(b[1]));
}
// L2-only cp.async (no L1 allocation)
__device__ __forceinline__ void cpa(uint32_t dst, const void* src) {
    asm volatile("cp.async.cg.shared.global [%0], [%1], 16;" :: "r"(dst), "l"(src) : "memory");
}
#define CPCOMMIT() asm volatile("cp.async.commit_group;" ::: "memory")
#define CPWAIT(n)  asm volatile("cp.async.wait_group %0;" :: "n"(n) : "memory")

__device__ __forceinline__ void fsplit2(float f, hf& h, hf& l) {
    h = __float2half_rn(f);
    l = __float2half_rn(f - __half2float(h));
}
__device__ __forceinline__ float pjoin(const hf* H, const hf* L, long i) {
    return __half2float(H[i]) + __half2float(L[i]);
}

// ---------------- smem geometry ----------------
#define APITCH 80
#define ASTG   (128*APITCH)              // 10240 (single A plane)

// ---------------- mma.sync fp16x2 fused (gather-)GEMM ----------------
// NB: block N tile; MW: m16-frags per warp; OCC: min CTAs/SM; NS: pipeline stages.
// 8 warps. Split-K: grid.z = #splits, K = per-split K; raw fp32 partial to Po.
template<int NB, int MW, int OCC, int NS>
__global__ __launch_bounds__(256, OCC)
void gemm_tc(const hf* __restrict__ Ah,
             const hf* __restrict__ Wh, const hf* __restrict__ Wl,
             hf* __restrict__ Oh, hf* __restrict__ Ol,
             float* __restrict__ Po, long pstride,
             const int* __restrict__ idx,
             const float* __restrict__ bias, const float* __restrict__ bias_b,
             const hf* __restrict__ Rh, const hf* __restrict__ Rl,
             int M, int N, int K, int lda, int ldn, int ldo, int ldr,
             int logC, int flags)
{
    constexpr int BP      = NB * 2 + 16;
    constexpr int BPL     = 32 * BP;
    constexpr int STG     = ASTG + 2 * BPL;
    constexpr int BCH     = 8 * NB;
    constexpr int WARPS_M = 128 / (MW * 16);
    static_assert(WARPS_M * (NB / 32) == 8, "8 warps");

    extern __shared__ char smem[];
    const uint32_t sbs = s2u(smem);
    const int t = threadIdx.x, wid = t >> 5, lane = t & 31;
    const int bm0 = blockIdx.x * 128, bn0 = blockIdx.y * NB;
    const int wm = (wid % WARPS_M) * (MW * 16), wn = (wid / WARPS_M) * 32;
    const int kbase = blockIdx.z * K;

    const int r0 = t >> 2, c4 = t & 3;
    const int cmask = (1 << logC) - 1;
    long ab[2]; const int* ib[2];
#pragma unroll
    for (int r = 0; r < 2; r++) {
        int m = bm0 + r0 + r * 64; if (m >= M) m = M - 1;
        int bI = m / VP, v = m - bI * VP;
        if (idx) { ab[r] = (long)bI * VP * lda; ib[r] = idx + v * LSP; }
        else     { ab[r] = (long)m * lda;       ib[r] = nullptr; }
    }

    const uint32_t la15 = lane & 15, lhi = lane >> 4, l7 = lane & 7, l8 = (lane >> 3) & 1;
    const int nkt = K >> 5;

    float acc[MW][4][4];
#pragma unroll
    for (int i = 0; i < MW; i++)
#pragma unroll
        for (int j = 0; j < 4; j++)
#pragma unroll
            for (int r = 0; r < 4; r++) acc[i][j][r] = 0.f;

    auto issue = [&](int kt) {
        const int k0 = kbase + (kt << 5);
        const uint32_t base = sbs + (kt % NS) * STG;
#pragma unroll
        for (int r = 0; r < 2; r++) {
            long off = idx ? (ab[r] + (long)ib[r][k0 >> logC] * lda + (k0 & cmask))
                           : (ab[r] + k0);
            cpa(base + (r0 + r * 64) * APITCH + c4 * 16, Ah + off + c4 * 8);
        }
#pragma unroll
        for (int i = t; i < BCH; i += 256) {
            const int pl  = i / (4 * NB);
            const int rem = i - pl * (4 * NB);
            const int row = rem / (NB / 8);
            const int col = rem - row * (NB / 8);
            const hf* Wp = pl ? Wl : Wh;
            cpa(base + ASTG + pl * BPL + row * BP + col * 16,
                Wp + (long)(k0 + row) * ldn + bn0 + col * 8);
        }
        CPCOMMIT();
    };

    // prologue: fill NS-1 stages
#pragma unroll
    for (int s = 0; s < NS - 1; s++) {
        if (s < nkt) issue(s); else CPCOMMIT();
    }

    for (int kt = 0; kt < nkt; kt++) {
        CPWAIT(NS - 2);
        __syncthreads();
        const uint32_t base = sbs + (kt % NS) * STG;
#pragma unroll
        for (int ks = 0; ks < 2; ks++) {
            uint32_t a[MW][4];
#pragma unroll
            for (int i = 0; i < MW; i++)
                ldsm4(base + (wm + i * 16 + la15) * APITCH + (ks * 16 + lhi * 8) * 2, a[i]);
            const uint32_t bo = base + ASTG + (uint32_t)(ks * 16 + l7 + l8 * 8) * BP
                               + (wn + lhi * 8) * 2;
            uint32_t bh[8], bl[8];
            ldsm4t(bo,            bh);
            ldsm4t(bo + 32,       bh + 4);
            ldsm4t(bo + BPL,      bl);
            ldsm4t(bo + BPL + 32, bl + 4);
#pragma unroll
            for (int i = 0; i < MW; i++)
#pragma unroll
                for (int nf = 0; nf < 4; nf++) mma_f16(acc[i][nf], a[i], bh + nf * 2);
#pragma unroll
            for (int i = 0; i < MW; i++)
#pragma unroll
                for (int nf = 0; nf < 4; nf++) mma_f16(acc[i][nf], a[i], bl + nf * 2);
        }
        if (kt + NS - 1 < nkt) issue(kt + NS - 1);
        else CPCOMMIT();
    }

    // ---- epilogue
    if (Po) {   // raw fp32 partial (split-K)
        float* P = Po + (long)blockIdx.z * pstride;
#pragma unroll
        for (int i = 0; i < MW; i++) {
#pragma unroll
            for (int hh = 0; hh < 2; hh++) {
                const int m = bm0 + wm + i * 16 + (lane >> 2) + hh * 8;
                if (m >= M) continue;
                const long orow = (long)m * ldo;
#pragma unroll
                for (int nf = 0; nf < 4; nf++) {
                    const int n = bn0 + wn + nf * 8 + 2 * (lane & 3);
                    float2 v2;
                    v2.x = acc[i][nf][hh * 2 + 0];
                    v2.y = acc[i][nf][hh * 2 + 1];
                    *(float2*)(P + orow + n) = v2;
                }
            }
        }
        return;
    }
    const bool wlo = (flags & F_WLO) != 0;
#pragma unroll
    for (int i = 0; i < MW; i++) {
#pragma unroll
        for (int hh = 0; hh < 2; hh++) {
            const int m = bm0 + wm + i * 16 + (lane >> 2) + hh * 8;
            if (m >= M) continue;
            const int bI = m / VP, v = m - bI * VP;
            const bool zd = (flags & F_ZDUM) && (v == V_);
            const long orow = (long)m * ldo;
            const long rrow = (long)m * ldr;
#pragma unroll
            for (int nf = 0; nf < 4; nf++) {
                const int n = bn0 + wn + nf * 8 + 2 * (lane & 3);
                float f0 = acc[i][nf][hh * 2 + 0];
                float f1 = acc[i][nf][hh * 2 + 1];
                if (bias)   { f0 += bias[n];            f1 += bias[n + 1]; }
                if (bias_b) { f0 += bias_b[bI * N + n]; f1 += bias_b[bI * N + n + 1]; }
                if (Rh)     { f0 += pjoin(Rh, Rl, rrow + n); f1 += pjoin(Rh, Rl, rrow + n + 1); }
                if (flags & F_RELU) { f0 = fmaxf(f0, 0.f); f1 = fmaxf(f1, 0.f); }
                if (zd) { f0 = 0.f; f1 = 0.f; }
                hf h0 = __float2half_rn(f0);
                hf h1 = __float2half_rn(f1);
                __half2 ph; ph.x = h0; ph.y = h1;
                *(__half2*)(Oh + orow + n) = ph;
                if (wlo) {
                    __half2 pl2;
                    pl2.x = __float2half_rn(f0 - __half2float(h0));
                    pl2.y = __float2half_rn(f1 - __half2float(h1));
                    *(__half2*)(Ol + orow + n) = pl2;
                }
            }
        }
    }
}

// ---------------- split-K combiner (vectorized x4) ----------------
__global__ void comb_k(const float* __restrict__ P0, const float* __restrict__ P1,
                       const float* __restrict__ bias,
                       const hf* __restrict__ Rh, const hf* __restrict__ Rl, int ldr,
                       hf* __restrict__ Oh)
{
    long q = (long)blockIdx.x * 256 + threadIdx.x;
    if (q >= (long)M_TOT * 64) return;
    long i = q * 4;
    int m = (int)(i >> 8), n = (int)(i & 255);
    int bI = m / VP, v = m - bI * VP;
    float4 a = *(const float4*)(P0 + i);
    float4 b = *(const float4*)(P1 + i);
    float4 c = *(const float4*)(bias + n);
    float f[4] = { a.x + b.x + c.x, a.y + b.y + c.y, a.z + b.z + c.z, a.w + b.w + c.w };
    if (Rh) {
        long r = (long)m * ldr + n;
        const __half2* rh = (const __half2*)(Rh + r);
        const __half2* rl = (const __half2*)(Rl + r);
        float2 h0 = __half22float2(rh[0]), h1 = __half22float2(rh[1]);
        float2 l0 = __half22float2(rl[0]), l1 = __half22float2(rl[1]);
        f[0] += h0.x + l0.x; f[1] += h0.y + l0.y;
        f[2] += h1.x + l1.x; f[3] += h1.y + l1.y;
    }
#pragma unroll
    for (int j = 0; j < 4; j++) {
        f[j] = fmaxf(f[j], 0.f);
        if (v == V_) f[j] = 0.f;
    }
    __half2 o0; o0.x = __float2half_rn(f[0]); o0.y = __float2half_rn(f[1]);
    __half2 o1; o1.x = __float2half_rn(f[2]); o1.y = __float2half_rn(f[3]);
    *(__half2*)(Oh + i)     = o0;
    *(__half2*)(Oh + i + 2) = o1;
}

// ---------------- prep kernels ----------------
__global__ void xprep(const float* __restrict__ x, hf* __restrict__ Xh)
{
    long i = (long)blockIdx.x * 256 + threadIdx.x;
    if (i >= (long)M_TOT * 512) return;
    int m = (int)(i >> 9), k = (int)(i & 511);
    int b = m / VP, v = m - b * VP;
    float val = 0.f;
    if (v < V_ && k < 479) val = x[((long)(b * V_ + v)) * 479 + k];
    Xh[i] = __float2half_rn(val);
}

#define NSEG 12
struct WSegs {
    const float* src[NSEG];
    hf* oh[NSEG]; hf* ol[NSEG];
    int N[NSEG]; int K[NSEG];
    long n[NSEG];
};
__global__ void wprep_all(WSegs s)
{
    const int seg = blockIdx.y;
    long i = (long)blockIdx.x * 256 + threadIdx.x;
    if (i >= s.n[seg]) return;
    const int N = s.N[seg];
    const int k = (int)(i / N);
    float v = (k < s.K[seg]) ? s.src[seg][i] : 0.f;
    fsplit2(v, s.oh[seg][i], s.ol[seg][i]);
}

// ---------------- maxpool / gterm / final ----------------
__global__ void maxpool1(const hf* __restrict__ fh, const hf* __restrict__ fl)
{
    int chunk = blockIdx.x, b = blockIdx.y, n = threadIdx.x;
    int v0 = chunk * 128;
    float m = -FLT_MAX;
    for (int i = 0; i < 128; i++) {
        int v = v0 + i;
        if (v < V_) m = fmaxf(m, pjoin(fh, fl, (long)(b * VP + v) * 128 + n));
    }
    g_part[(b * NCHUNK + chunk) * 128 + n] = m;
}
__global__ void maxpool2()
{
    int b = blockIdx.x, n = threadIdx.x;
    float m = -FLT_MAX;
    for (int c = 0; c < NCHUNK; c++) m = fmaxf(m, g_part[(b * NCHUNK + c) * 128 + n]);
    g_gfs[b * 128 + n] = m;
}
__global__ void gterm_k(const float* __restrict__ Wo1)
{
    int b = blockIdx.x, n = threadIdx.x;
    float s = 0.f;
    for (int c = 0; c < 128; c++)
        s = fmaf(g_gfs[b * 128 + c], Wo1[(384 + c) * 256 + n], s);
    g_gterm[b * 256 + n] = s;
}
__global__ void out_k(const hf* __restrict__ h2h, const hf* __restrict__ h2l,
                      const float* __restrict__ Wo3, const float* __restrict__ bo3,
                      float* __restrict__ out)
{
    __shared__ float w[384];
    int t = threadIdx.x;
    if (t < 128) { w[t] = Wo3[t]; w[t + 128] = Wo3[t + 128]; w[t + 256] = Wo3[t + 256]; }
    __syncthreads();
    int warp = t >> 5, lane = t & 31;
    int u = blockIdx.x * 4 + warp;
    if (u >= BB * V_) return;
    int b = u / V_, v = u - b * V_;
    long row = (long)(b * VP + v) * 128;
    float s0 = 0.f, s1 = 0.f, s2 = 0.f;
    for (int c = lane; c < 128; c += 32) {
        float h = pjoin(h2h, h2l, row + c);
        s0 = fmaf(h, w[c * 3 + 0], s0);
        s1 = fmaf(h, w[c * 3 + 1], s1);
        s2 = fmaf(h, w[c * 3 + 2], s2);
    }
    for (int o = 16; o > 0; o >>= 1) {
        s0 += __shfl_down_sync(0xffffffffu, s0, o);
        s1 += __shfl_down_sync(0xffffffffu, s1, o);
        s2 += __shfl_down_sync(0xffffffffu, s2, o);
    }
    if (lane == 0) {
        out[u * 3 + 0] = s0 + bo3[0];
        out[u * 3 + 1] = s1 + bo3[1];
        out[u * 3 + 2] = s2 + bo3[2];
    }
}

// ---------------- host orchestration ----------------
static void* sym(const void* s) { void* p; cudaGetSymbolAddress(&p, s); return p; }

#define SMEM128 (4*(ASTG + 2*32*(128*2+16)))   // 110592 (4-stage)
#define SMEM64  (3*(ASTG + 2*32*(64*2+16)))    // 58368  (3-stage)
#define PSTRIDE ((long)M_TOT*256)

static void G128(const hf* Ah, const hf* Wh, const hf* Wl,
                 hf* Oh, hf* Ol, const int* idx, const float* bias, const float* bb,
                 const hf* Rh, const hf* Rl,
                 int N, int K, int lda, int ldn, int ldo, int ldr, int logC, int flags)
{
    dim3 grid((M_TOT + 127) / 128, N / 128, 1);
    gemm_tc<128, 4, 2, 4><<<grid, 256, SMEM128>>>(Ah, Wh, Wl, Oh, Ol, nullptr, 0,
        idx, bias, bb, Rh, Rl, M_TOT, N, K, lda, ldn, ldo, ldr, logC, flags);
}
// split-K x2, raw fp32 partials
static void G128S(const hf* Ah, const hf* Wh, const hf* Wl, float* Po,
                  const int* idx, int N, int Khalf, int lda, int ldn, int logC)
{
    dim3 grid((M_TOT + 127) / 128, N / 128, 2);
    gemm_tc<128, 4, 2, 4><<<grid, 256, SMEM128>>>(Ah, Wh, Wl, nullptr, nullptr, Po, PSTRIDE,
        idx, nullptr, nullptr, nullptr, nullptr, M_TOT, N, Khalf, lda, ldn, N, 0, logC, 0);
}
static void G64(const hf* Ah, const hf* Wh, const hf* Wl,
                hf* Oh, hf* Ol, const int* idx, const float* bias, const float* bb,
                const hf* Rh, const hf* Rl,
                int N, int K, int lda, int ldn, int ldo, int ldr, int logC, int flags)
{
    dim3 grid((M_TOT + 127) / 128, N / 64, 1);
    gemm_tc<64, 2, 3, 3><<<grid, 256, SMEM64>>>(Ah, Wh, Wl, Oh, Ol, nullptr, 0,
        idx, bias, bb, Rh, Rl, M_TOT, N, K, lda, ldn, ldo, ldr, logC, flags);
}

extern "C" void kernel_launch(void* const* d_in, const int* in_sizes, int n_in,
                              void* d_out, int out_size)
{
    (void)in_sizes; (void)n_in; (void)out_size;
    const float* x       = (const float*)d_in[0];
    const int*   sidx    = (const int*)  d_in[1];
    const float* W_point = (const float*)d_in[2];
    const float* res1_W  = (const float*)d_in[3];
    const float* res1_b  = (const float*)d_in[4];
    const float* W_mid   = (const float*)d_in[5];
    const float* ress_W  = (const float*)d_in[6];
    const float* ress_b  = (const float*)d_in[7];
    const float* Wo1     = (const float*)d_in[8];
    const float* bo1     = (const float*)d_in[9];
    const float* Wo2     = (const float*)d_in[10];
    const float* bo2     = (const float*)d_in[11];
    const float* Wo3     = (const float*)d_in[12];
    const float* bo3     = (const float*)d_in[13];
    float* out = (float*)d_out;

    cudaFuncSetAttribute((const void*)gemm_tc<128, 4, 2, 4>,
                         cudaFuncAttributeMaxDynamicSharedMemorySize, SMEM128);
    cudaFuncSetAttribute((const void*)gemm_tc<64, 2, 3, 3>,
                         cudaFuncAttributeMaxDynamicSharedMemorySize, SMEM64);

    hf *Xh = (hf*)sym(g_Xh);
    hf *Hbh = (hf*)sym(g_Hbh), *Hbl = (hf*)sym(g_Hbl);
    hf *T1h = (hf*)sym(g_T1h);
    hf *T2h = (hf*)sym(g_T2h);
    hf *F1h = (hf*)sym(g_F1h), *F1l = (hf*)sym(g_F1l);
    hf *F2h = (hf*)sym(g_F2h);
    hf *H2h = (hf*)sym(g_H2h), *H2l = (hf*)sym(g_H2l);
    hf *Wpth = (hf*)sym(g_Wpth), *Wptl = (hf*)sym(g_Wptl);
    hf *R1ah = (hf*)sym(g_R1ah), *R1al = (hf*)sym(g_R1al);
    hf *R1bh = (hf*)sym(g_R1bh), *R1bl = (hf*)sym(g_R1bl);
    hf *Wmh  = (hf*)sym(g_Wmh),  *Wml  = (hf*)sym(g_Wml);
    hf *RSh  = (hf*)sym(g_RSh),  *RSl  = (hf*)sym(g_RSl);
    hf *Wo1h = (hf*)sym(g_Wo1h), *Wo1l = (hf*)sym(g_Wo1l);
    hf *Wo2h = (hf*)sym(g_Wo2h), *Wo2l = (hf*)sym(g_Wo2l);
    float* gterm = (float*)sym(g_gterm);
    float* P = (float*)sym(g_P);
    float* P0 = P;
    float* P1 = P + PSTRIDE;

    // ---- prep
    xprep<<<(unsigned)(((long)M_TOT * 512 + 255) / 256), 256>>>(x, Xh);
    {
        WSegs s;
        int si = 0;
        auto add = [&](const float* src, hf* oh, hf* ol, int K, int N, int Kpad) {
            s.src[si] = src; s.oh[si] = oh; s.ol[si] = ol;
            s.N[si] = N; s.K[si] = K; s.n[si] = (long)Kpad * N; si++;
        };
        add(W_point, Wpth, Wptl, 479, 256, 512);
        add(res1_W,              R1ah, R1al, 4096, 256, 4096);
        add(res1_W + 4096 * 256, R1bh, R1bl, 4096, 256, 4096);
        add(W_mid, Wmh, Wml, 256, 128, 256);
        for (int j = 0; j < 6; j++)
            add(ress_W + (long)j * 2048 * 128, RSh + (long)j * 2048 * 128,
                RSl + (long)j * 2048 * 128, 2048, 128, 2048);
        add(Wo1, Wo1h, Wo1l, 384, 256, 384);
        add(Wo2, Wo2h, Wo2l, 256, 128, 256);
        wprep_all<<<dim3(4096, NSEG), 256>>>(s);
    }

    const unsigned CBLK = (unsigned)(((long)M_TOT * 64 + 255) / 256);

    // 1) pfs = relu(x @ W_point) -> Hb cols 0:256
    G128(Xh, Wpth, Wptl, Hbh, Hbl, nullptr, nullptr, nullptr, nullptr, nullptr,
         256, 512, 512, 256, 384, 0, 0, F_RELU | F_ZDUM | F_WLO);
    // 2) res1 conv1 (K=4096) — split-K x2 + combine
    G128S(Hbh, R1ah, R1al, P, sidx, 256, 2048, 384, 256, 8);
    comb_k<<<CBLK, 256>>>(P0, P1, res1_b, nullptr, nullptr, 0, T1h);
    // 3) res1 conv2 + residual(pfs) — split-K x2 + combine
    G128S(T1h, R1bh, R1bl, P, sidx, 256, 2048, 256, 256, 8);
    comb_k<<<CBLK, 256>>>(P0, P1, res1_b + 256, Hbh, Hbl, 384, T2h);
    // 4) fs = (r1 @ W_mid) * zp
    G64(T2h, Wmh, Wml, F1h, F1l, nullptr, nullptr, nullptr, nullptr, nullptr,
        128, 256, 256, 128, 128, 0, 0, F_ZDUM | F_WLO);
    // 5) masked global max-pool
    maxpool1<<<dim3(NCHUNK, BB), 128>>>(F1h, F1l);
    maxpool2<<<BB, 128>>>();
    // 6) three residual blocks (C=128); block 3 conv2 writes Hb cols 256:384
    for (int i = 0; i < 3; i++) {
        const hf* W0h = RSh + (long)(i * 2 + 0) * 2048 * 128;
        const hf* W0l = RSl + (long)(i * 2 + 0) * 2048 * 128;
        const hf* W1h = RSh + (long)(i * 2 + 1) * 2048 * 128;
        const hf* W1l = RSl + (long)(i * 2 + 1) * 2048 * 128;
        const float* b0 = ress_b + (i * 2 + 0) * 128;
        const float* b1 = ress_b + (i * 2 + 1) * 128;
        G64(F1h, W0h, W0l, F2h, nullptr, sidx, b0, nullptr, nullptr, nullptr,
            128, 2048, 128, 128, 128, 0, 7, F_RELU | F_ZDUM);
        if (i < 2)
            G64(F2h, W1h, W1l, F1h, F1l, sidx, b1, nullptr, F1h, F1l,
                128, 2048, 128, 128, 128, 128, 7, F_RELU | F_ZDUM | F_WLO);
        else
            G64(F2h, W1h, W1l, Hbh + 256, nullptr, sidx, b1, nullptr, F1h, F1l,
                128, 2048, 128, 128, 384, 128, 7, F_RELU | F_ZDUM);
    }
    // 7) gterm[b] = gfs[b] @ Wo1[384:512]
    gterm_k<<<BB, 256>>>(Wo1);
    // 8) h1 = relu([pfs|fs] @ Wo1[0:384] + bo1 + gterm)
    G128(Hbh, Wo1h, Wo1l, T1h, nullptr, nullptr, bo1, gterm, nullptr, nullptr,
         256, 384, 384, 256, 256, 0, 0, F_RELU);
    // 9) h2 = relu(h1 @ Wo2 + bo2)
    G64(T1h, Wo2h, Wo2l, H2h, H2l, nullptr, bo2, nullptr, nullptr, nullptr,
        128, 256, 256, 128, 128, 0, 0, F_RELU | F_WLO);
    // 10) out = h2 @ Wo3 + bo3
    out_k<<<(BB * V_ + 3) / 4, 128>>>(H2h, H2l, Wo3, bo3, out);
}